// round 9
// baseline (speedup 1.0000x reference)
#include <cuda_runtime.h>

#define BB   2
#define HH   8
#define PP   128
#define HIDD 1024
#define KWIN 32

__global__ void __launch_bounds__(256, 1)
k_fused(const float* __restrict__ hidden,
        const float* __restrict__ dt_W,
        const float* __restrict__ dt_b,
        const float* __restrict__ g_W,
        const float* __restrict__ g_bv,
        const float* __restrict__ A_log,
        const float* __restrict__ Dv,
        const float* __restrict__ dt_bias,
        const float* __restrict__ norm_w,
        const float* __restrict__ o_W,
        const float* __restrict__ o_bv,
        float* __restrict__ out, int T) {
    int b = blockIdx.x >> 3, h = blockIdx.x & 7;
    int tid = threadIdx.x, warp = tid >> 5, lane = tid & 31;
    int q = tid & 127, hf = tid >> 7;
    int s0 = T - KWIN;

    // 16B-aligned: these are accessed through float4*
    __shared__ __align__(16) float xlast_s[HIDD];   // last hidden row (4 KB)
    __shared__ __align__(16) float zall[HIDD];      // normalized z (4 KB)
    __shared__ __align__(16) float dte_s [HH][KWIN];
    __shared__ __align__(16) float dots_s[HH][KWIN];
    __shared__ __align__(16) float wv_s  [HH][KWIN];
    __shared__ __align__(16) float part[2][PP];
    // scalar-ish shared state (kept after the aligned arrays)
    __shared__ float silu_sh[HH];
    __shared__ float bias_sh[HH];
    __shared__ float d_sh[HH];
    __shared__ float red[8];
    __shared__ float scsh;

    // ---- o_W prefetch: cold DRAM latency overlaps everything below ----
    float Wreg[64];
    {
        const float* Wp = o_W + ((size_t)h * PP + hf * 64) * PP + q;
        #pragma unroll
        for (int i = 0; i < 64; i++) Wreg[i] = Wp[(size_t)i * PP];
    }

    {
        const float4* xl4 = (const float4*)(hidden + ((size_t)b * T + T - 1) * HIDD);
        ((float4*)xlast_s)[tid] = xl4[tid];
        if (tid < HH) {
            bias_sh[tid] = dt_b[tid] + dt_bias[tid];
            d_sh[tid]    = Dv[tid];
        }
    }
    __syncthreads();

    // ---- Gate silu: one warp per head (g_W straight from global) ----
    {
        const float4* xl4 = (const float4*)xlast_s;
        const float4* w4  = (const float4*)(g_W + (size_t)warp * HIDD);
        float v = 0.f;
        #pragma unroll
        for (int k = 0; k < 8; k++) {
            float4 a = xl4[lane + 32 * k], w = w4[lane + 32 * k];
            v += a.x * w.x + a.y * w.y + a.z * w.z + a.w * w.w;
        }
        #pragma unroll
        for (int o = 16; o > 0; o >>= 1) v += __shfl_xor_sync(0xffffffffu, v, o);
        if (lane == 0) {
            float g = tanhf(v + g_bv[warp]);
            silu_sh[warp] = g / (1.f + __expf(-g));
        }
    }

    // ---- Phase A: dte + dots for ALL heads, 4 row-passes (warp = row) ----
    // float4 index i = lane+32k spans exactly head k -> dots ride along free.
    const float4* dtW4 = (const float4*)dt_W;
    #pragma unroll
    for (int j = 0; j < 4; j++) {
        int s = j * 8 + warp;
        const float4* xr4 = (const float4*)(hidden + ((size_t)b * T + s0 + s) * HIDD);
        const float4* xw4 = (const float4*)xlast_s;
        float v[HH], dd[HH];
        #pragma unroll
        for (int hh = 0; hh < 8; hh++) { v[hh] = 0.f; }
        #pragma unroll
        for (int k = 0; k < 8; k++) {
            float4 a  = xr4[lane + 32 * k];
            float4 xw = xw4[lane + 32 * k];
            dd[k] = a.x * xw.x + a.y * xw.y + a.z * xw.z + a.w * xw.w;
            #pragma unroll
            for (int hh = 0; hh < 8; hh++) {
                float4 w = dtW4[hh * 256 + lane + 32 * k];
                v[hh] += a.x * w.x + a.y * w.y + a.z * w.z + a.w * w.w;
            }
        }
        #pragma unroll
        for (int hh = 0; hh < 8; hh++) {
            #pragma unroll
            for (int o = 16; o > 0; o >>= 1) {
                v[hh]  += __shfl_xor_sync(0xffffffffu, v[hh],  o);
                dd[hh] += __shfl_xor_sync(0xffffffffu, dd[hh], o);
            }
        }
        if (lane < HH)            dte_s [lane][s]      = v[lane] + bias_sh[lane];
        else if (lane < 2 * HH)   dots_s[lane - HH][s] = dd[lane - HH];
    }
    __syncthreads();

    // ---- Warp-local suffix scan per head (warp = head) ----
    {
        float Ah  = -__expf(A_log[warp]);
        float dte = dte_s[warp][lane];
        float dA  = dte * Ah;
        float S   = dA;
        #pragma unroll
        for (int o = 1; o < 32; o <<= 1) {
            float t = __shfl_down_sync(0xffffffffu, S, o);
            if (lane + o < 32) S += t;
        }
        // c[s] = S[s] - dA[s] = sum_{r>s} dA[r]
        wv_s[warp][lane] = dots_s[warp][lane] * __expf(S - dA) * dte;
    }
    __syncthreads();

    // ---- y-pass: thread = one float4 column of the 1024-wide row ----
    int hd = tid >> 5;                        // head of this column group
    float4 y4 = make_float4(0.f, 0.f, 0.f, 0.f);
    {
        const float4* base4 = (const float4*)(hidden + ((size_t)b * T + s0) * HIDD);
        #pragma unroll 8
        for (int s = 0; s < KWIN; s++) {
            float w = wv_s[hd][s];
            float4 a = base4[s * 256 + tid];   // L1-hot from Phase A
            y4.x += w * a.x; y4.y += w * a.y; y4.z += w * a.z; y4.w += w * a.w;
        }
        float dcoef = d_sh[hd];
        float4 xl = ((const float4*)xlast_s)[tid];
        y4.x += dcoef * xl.x; y4.y += dcoef * xl.y; y4.z += dcoef * xl.z; y4.w += dcoef * xl.w;
    }

    // ---- RMS over all 1024 gated values (all in-block) ----
    float sg = silu_sh[hd];
    float4 z4 = make_float4(y4.x * sg, y4.y * sg, y4.z * sg, y4.w * sg);
    float ssq = z4.x * z4.x + z4.y * z4.y + z4.z * z4.z + z4.w * z4.w;
    #pragma unroll
    for (int o = 16; o > 0; o >>= 1) ssq += __shfl_xor_sync(0xffffffffu, ssq, o);
    if (lane == 0) red[warp] = ssq;
    __syncthreads();
    if (tid == 0) {
        float s = 0.f;
        #pragma unroll
        for (int i = 0; i < 8; i++) s += red[i];
        scsh = rsqrtf(s / (float)HIDD + 1e-5f);
    }
    __syncthreads();
    {
        float sc = scsh;
        float4 nw = ((const float4*)norm_w)[tid];
        z4.x *= sc * nw.x; z4.y *= sc * nw.y; z4.z *= sc * nw.z; z4.w *= sc * nw.w;
        ((float4*)zall)[tid] = z4;
    }
    __syncthreads();

    // ---- Own-head projection with register-resident o_W tile ----
    float acc = 0.f;
    #pragma unroll
    for (int i = 0; i < 64; i++) acc += Wreg[i] * zall[h * PP + hf * 64 + i];
    part[hf][q] = acc;
    __syncthreads();
    if (tid < PP)
        out[b * HIDD + h * PP + tid] = part[0][tid] + part[1][tid] + o_bv[h * PP + tid];
}

extern "C" void kernel_launch(void* const* d_in, const int* in_sizes, int n_in,
                              void* d_out, int out_size) {
    const float* hidden  = (const float*)d_in[0];
    const float* dt_W    = (const float*)d_in[1];
    const float* dt_b    = (const float*)d_in[2];
    const float* g_W     = (const float*)d_in[3];
    const float* g_bv    = (const float*)d_in[4];
    const float* A_log   = (const float*)d_in[5];
    const float* Dv      = (const float*)d_in[6];
    const float* dt_bias = (const float*)d_in[7];
    const float* norm_w  = (const float*)d_in[8];
    const float* o_W     = (const float*)d_in[9];
    const float* o_bv    = (const float*)d_in[10];

    int T = in_sizes[0] / (BB * HIDD);   // 4096

    k_fused<<<BB * HH, 256>>>(hidden, dt_W, dt_b, g_W, g_bv, A_log, Dv,
                              dt_bias, norm_w, o_W, o_bv, (float*)d_out, T);
}

// round 10
// speedup vs baseline: 2.1521x; 2.1521x over previous
#include <cuda_runtime.h>
#include <cstdint>

#define BB   2
#define HH   8
#define PP   128
#define HIDD 1024
#define KWIN 32

// Dynamic smem layout (float offsets); all float4-accessed regions 16B aligned.
#define OW_OFF   0                      // 16384 floats (64 KB) o_W[h]
#define DTW_OFF  16384                  // 1024 dt_W[h]
#define XL_OFF   17408                  // 1024 last hidden row
#define DTE_OFF  18432                  // 32
#define DOTS_OFF (DTE_OFF + 32)         // 32
#define WV_OFF   (DOTS_OFF + 32)        // 32
#define ZSH_OFF  (WV_OFF + 32)          // 128
#define PART_OFF (ZSH_OFF + 128)        // 256
#define SILU_OFF (PART_OFF + 256)       // 8
#define RED_OFF  (SILU_OFF + 8)         // 8
#define SC_OFF   (RED_OFF + 8)          // 4 (1 used)
#define SMEM_FLOATS (SC_OFF + 4)
#define SMEM_BYTES  (SMEM_FLOATS * 4)

__device__ __align__(16) float g_y[BB][HH][PP];
__device__ unsigned g_c1[BB];           // monotonic arrival counter (never reset)

__global__ void __launch_bounds__(256, 1)
k_fused(const float* __restrict__ hidden,
        const float* __restrict__ dt_W,
        const float* __restrict__ dt_b,
        const float* __restrict__ g_W,
        const float* __restrict__ g_bv,
        const float* __restrict__ A_log,
        const float* __restrict__ Dv,
        const float* __restrict__ dt_bias,
        const float* __restrict__ norm_w,
        const float* __restrict__ o_W,
        const float* __restrict__ o_bv,
        float* __restrict__ out, int T) {
    extern __shared__ __align__(16) float sm[];
    __shared__ unsigned my_sh;

    int b = blockIdx.x >> 3, h = blockIdx.x & 7;
    int tid = threadIdx.x, warp = tid >> 5, lane = tid & 31;
    int q = tid & 127, hf = tid >> 7;
    int s0 = T - KWIN;

    // ---- cp.async: o_W[h] 64 KB -> smem, fully async until the projection ----
    {
        const float4* src = (const float4*)(o_W + (size_t)h * PP * PP);
        uint32_t dst = (uint32_t)__cvta_generic_to_shared(sm + OW_OFF);
        #pragma unroll
        for (int c = 0; c < 16; c++) {
            uint32_t d = dst + (uint32_t)(tid + c * 256) * 16u;
            const float4* s = src + tid + c * 256;
            asm volatile("cp.async.cg.shared.global [%0], [%1], 16;\n" :: "r"(d), "l"(s));
        }
        asm volatile("cp.async.commit_group;\n" ::: "memory");
    }

    // ---- Stage dt_W[h] + last hidden row ----
    ((float4*)(sm + DTW_OFF))[tid] = ((const float4*)(dt_W + (size_t)h * HIDD))[tid];
    ((float4*)(sm + XL_OFF))[tid]  = ((const float4*)(hidden + ((size_t)b * T + T - 1) * HIDD))[tid];
    __syncthreads();

    float bias = dt_b[h] + dt_bias[h];
    float Ah   = -__expf(A_log[h]);

    // ---- Gate silu: one warp per head (needed block-locally for RMS) ----
    {
        const float4* xl4 = (const float4*)(sm + XL_OFF);
        const float4* w4  = (const float4*)(g_W + (size_t)warp * HIDD);
        float v = 0.f;
        #pragma unroll
        for (int k = 0; k < 8; k++) {
            float4 a = xl4[lane + 32 * k], w = w4[lane + 32 * k];
            v += a.x * w.x + a.y * w.y + a.z * w.z + a.w * w.w;
        }
        #pragma unroll
        for (int o = 16; o > 0; o >>= 1) v += __shfl_xor_sync(0xffffffffu, v, o);
        if (lane == 0) {
            float g = tanhf(v + g_bv[warp]);
            sm[SILU_OFF + warp] = g / (1.f + __expf(-g));
        }
    }

    // ---- Phase A: own-head dte + dots over all 32 rows (4 rows per warp) ----
    // float4 index lane+32k: the k==h iteration is exactly head h's slice,
    // so dots[s] = x_s[h-slice] . xlast[h-slice] rides along free.
    {
        const float4* w4  = (const float4*)(sm + DTW_OFF);
        const float4* xl4 = (const float4*)(sm + XL_OFF);
        #pragma unroll
        for (int j = 0; j < 4; j++) {
            int s = warp + 8 * j;
            const float4* xr4 = (const float4*)(hidden + ((size_t)b * T + s0 + s) * HIDD);
            float v = 0.f, d = 0.f;
            #pragma unroll
            for (int k = 0; k < 8; k++) {
                float4 a = xr4[lane + 32 * k];
                float4 w = w4[lane + 32 * k];
                v += a.x * w.x + a.y * w.y + a.z * w.z + a.w * w.w;
                if (k == h) {
                    float4 xw = xl4[lane + 32 * k];
                    d += a.x * xw.x + a.y * xw.y + a.z * xw.z + a.w * xw.w;
                }
            }
            #pragma unroll
            for (int o = 16; o > 0; o >>= 1) {
                v += __shfl_xor_sync(0xffffffffu, v, o);
                d += __shfl_xor_sync(0xffffffffu, d, o);
            }
            if (lane == 0) { sm[DTE_OFF + s] = v + bias; sm[DOTS_OFF + s] = d; }
        }
    }
    __syncthreads();

    // ---- Suffix scan + window weights (warp 0, own head) ----
    if (warp == 0) {
        float dte = sm[DTE_OFF + lane];
        float dA  = dte * Ah;
        float S   = dA;
        #pragma unroll
        for (int o = 1; o < 32; o <<= 1) {
            float t = __shfl_down_sync(0xffffffffu, S, o);
            if (lane + o < 32) S += t;
        }
        // c[s] = S - dA = sum_{r>s} dA[r]
        sm[WV_OFF + lane] = sm[DOTS_OFF + lane] * __expf(S - dA) * dte;
    }
    __syncthreads();

    // ---- y-pass: own head, rows L1-hot from Phase A ----
    {
        const float* base = hidden + ((size_t)b * T + s0 + hf * 16) * HIDD + h * PP + q;
        float acc = 0.f;
        #pragma unroll
        for (int s = 0; s < 16; s++) acc += sm[WV_OFF + hf * 16 + s] * base[(size_t)s * HIDD];
        sm[PART_OFF + hf * 128 + q] = acc;
    }
    __syncthreads();
    if (tid < PP)
        g_y[b][h][tid] = sm[PART_OFF + tid] + sm[PART_OFF + 128 + tid]
                       + Dv[h] * sm[XL_OFF + h * PP + tid];
    __threadfence();
    __syncthreads();
    if (tid == 0) my_sh = atomicAdd(&g_c1[b], 1u);
    __syncthreads();

    // ---- Single grid barrier (monotonic, reset-free; proven in R5/R6) ----
    if (tid == 0) {
        unsigned target = ((my_sh >> 3) + 1u) << 3;
        volatile unsigned* c = &g_c1[b];
        while (*c < target) {}
    }
    __syncthreads();
    __threadfence();

    // ---- RMS over all 1024 gated values (redundant per block, 4 KB read) ----
    float ssq;
    {
        int hd = tid >> 5;                          // head of this float4
        float sg = sm[SILU_OFF + hd];
        float4 yv = __ldcg(((const float4*)&g_y[b][0][0]) + tid);
        float zx = yv.x * sg, zy = yv.y * sg, zz = yv.z * sg, zw = yv.w * sg;
        ssq = zx * zx + zy * zy + zz * zz + zw * zw;
    }
    #pragma unroll
    for (int o = 16; o > 0; o >>= 1) ssq += __shfl_xor_sync(0xffffffffu, ssq, o);
    if (lane == 0) sm[RED_OFF + warp] = ssq;
    __syncthreads();
    if (tid == 0) {
        float s = 0.f;
        #pragma unroll
        for (int i = 0; i < 8; i++) s += sm[RED_OFF + i];
        sm[SC_OFF] = rsqrtf(s / (float)HIDD + 1e-5f);
    }
    __syncthreads();

    // ---- Own-head normalized z ----
    if (tid < PP)
        sm[ZSH_OFF + tid] = g_y[b][h][tid] * sm[SILU_OFF + h] * sm[SC_OFF]
                          * norm_w[h * PP + tid];

    // ---- Projection from the cp.async-staged o_W tile ----
    asm volatile("cp.async.wait_group 0;\n" ::: "memory");
    __syncthreads();
    {
        float acc = 0.f;
        const float* oW = sm + OW_OFF;
        #pragma unroll
        for (int i = 0; i < 64; i++)
            acc += oW[(hf * 64 + i) * PP + q] * sm[ZSH_OFF + hf * 64 + i];
        sm[PART_OFF + hf * 128 + q] = acc;
    }
    __syncthreads();
    if (tid < PP)
        out[b * HIDD + h * PP + tid] = sm[PART_OFF + tid] + sm[PART_OFF + 128 + tid]
                                     + o_bv[h * PP + tid];
}

extern "C" void kernel_launch(void* const* d_in, const int* in_sizes, int n_in,
                              void* d_out, int out_size) {
    const float* hidden  = (const float*)d_in[0];
    const float* dt_W    = (const float*)d_in[1];
    const float* dt_b    = (const float*)d_in[2];
    const float* g_W     = (const float*)d_in[3];
    const float* g_bv    = (const float*)d_in[4];
    const float* A_log   = (const float*)d_in[5];
    const float* Dv      = (const float*)d_in[6];
    const float* dt_bias = (const float*)d_in[7];
    const float* norm_w  = (const float*)d_in[8];
    const float* o_W     = (const float*)d_in[9];
    const float* o_bv    = (const float*)d_in[10];

    int T = in_sizes[0] / (BB * HIDD);   // 4096

    cudaFuncSetAttribute(k_fused, cudaFuncAttributeMaxDynamicSharedMemorySize, SMEM_BYTES);
    k_fused<<<BB * HH, 256, SMEM_BYTES>>>(hidden, dt_W, dt_b, g_W, g_bv, A_log, Dv,
                                          dt_bias, norm_w, o_W, o_bv, (float*)d_out, T);
}

// round 11
// speedup vs baseline: 2.2405x; 1.0411x over previous
#include <cuda_runtime.h>
#include <cstdint>

#define BB   2
#define HH   8
#define PP   128
#define HIDD 1024
#define KWIN 32

// Dynamic smem layout (float offsets); float4-accessed regions 16B aligned.
#define OW_OFF   0                      // 16384 floats (64 KB) o_W[h]
#define DTW_OFF  16384                  // 1024 dt_W[h]
#define XL_OFF   17408                  // 1024 last hidden row
#define YALL_OFF 18432                  // 1024 y for all 8 heads (DSMEM target)
#define DTE_OFF  19456                  // 32
#define DOTS_OFF (DTE_OFF + 32)         // 32
#define WV_OFF   (DOTS_OFF + 32)        // 32
#define ZSH_OFF  (WV_OFF + 32)          // 128
#define PART_OFF (ZSH_OFF + 128)        // 256
#define SILU_OFF (PART_OFF + 256)       // 8
#define RED_OFF  (SILU_OFF + 8)         // 8
#define SC_OFF   (RED_OFF + 8)          // 4 (1 used)
#define SMEM_FLOATS (SC_OFF + 4)
#define SMEM_BYTES  (SMEM_FLOATS * 4)

__device__ __forceinline__ void dsmem_store_f32(uint32_t local_addr, int rank, float val) {
    uint32_t remote;
    asm volatile("mapa.shared::cluster.u32 %0, %1, %2;\n"
                 : "=r"(remote) : "r"(local_addr), "r"(rank));
    asm volatile("st.shared::cluster.f32 [%0], %1;\n" :: "r"(remote), "f"(val));
}

__global__ void __launch_bounds__(256, 1) __cluster_dims__(HH, 1, 1)
k_fused(const float* __restrict__ hidden,
        const float* __restrict__ dt_W,
        const float* __restrict__ dt_b,
        const float* __restrict__ g_W,
        const float* __restrict__ g_bv,
        const float* __restrict__ A_log,
        const float* __restrict__ Dv,
        const float* __restrict__ dt_bias,
        const float* __restrict__ norm_w,
        const float* __restrict__ o_W,
        const float* __restrict__ o_bv,
        float* __restrict__ out, int T) {
    extern __shared__ __align__(16) float sm[];

    int b = blockIdx.x >> 3, h = blockIdx.x & 7;   // h == cluster rank
    int tid = threadIdx.x, warp = tid >> 5, lane = tid & 31;
    int q = tid & 127, hf = tid >> 7;
    int s0 = T - KWIN;

    // ---- cp.async: o_W[h] 64 KB -> smem, fully async until the projection ----
    {
        const float4* src = (const float4*)(o_W + (size_t)h * PP * PP);
        uint32_t dst = (uint32_t)__cvta_generic_to_shared(sm + OW_OFF);
        #pragma unroll
        for (int c = 0; c < 16; c++) {
            uint32_t d = dst + (uint32_t)(tid + c * 256) * 16u;
            const float4* s = src + tid + c * 256;
            asm volatile("cp.async.cg.shared.global [%0], [%1], 16;\n" :: "r"(d), "l"(s));
        }
        asm volatile("cp.async.commit_group;\n" ::: "memory");
    }

    // ---- Stage dt_W[h] + last hidden row ----
    ((float4*)(sm + DTW_OFF))[tid] = ((const float4*)(dt_W + (size_t)h * HIDD))[tid];
    ((float4*)(sm + XL_OFF))[tid]  = ((const float4*)(hidden + ((size_t)b * T + T - 1) * HIDD))[tid];
    __syncthreads();

    float bias = dt_b[h] + dt_bias[h];
    float Ah   = -__expf(A_log[h]);

    // ---- Phase A: own-head dte + dots over all 32 rows (4 rows per warp) ----
    // float4 index lane+32k: the k==h iteration is exactly head h's slice,
    // so dots[s] = x_s[h-slice] . xlast[h-slice] rides along free.
    {
        const float4* w4  = (const float4*)(sm + DTW_OFF);
        const float4* xl4 = (const float4*)(sm + XL_OFF);
        #pragma unroll
        for (int j = 0; j < 4; j++) {
            int s = warp + 8 * j;
            const float4* xr4 = (const float4*)(hidden + ((size_t)b * T + s0 + s) * HIDD);
            float v = 0.f, d = 0.f;
            #pragma unroll
            for (int k = 0; k < 8; k++) {
                float4 a = xr4[lane + 32 * k];
                float4 w = w4[lane + 32 * k];
                v += a.x * w.x + a.y * w.y + a.z * w.z + a.w * w.w;
                if (k == h) {
                    float4 xw = xl4[lane + 32 * k];
                    d += a.x * xw.x + a.y * xw.y + a.z * xw.z + a.w * xw.w;
                }
            }
            #pragma unroll
            for (int o = 16; o > 0; o >>= 1) {
                v += __shfl_xor_sync(0xffffffffu, v, o);
                d += __shfl_xor_sync(0xffffffffu, d, o);
            }
            if (lane == 0) { sm[DTE_OFF + s] = v + bias; sm[DOTS_OFF + s] = d; }
        }
    }
    __syncthreads();

    // ---- Suffix scan + window weights (warp 0, own head) ----
    if (warp == 0) {
        float dte = sm[DTE_OFF + lane];
        float dA  = dte * Ah;
        float S   = dA;
        #pragma unroll
        for (int o = 1; o < 32; o <<= 1) {
            float t = __shfl_down_sync(0xffffffffu, S, o);
            if (lane + o < 32) S += t;
        }
        // c[s] = S - dA = sum_{r>s} dA[r]
        sm[WV_OFF + lane] = sm[DOTS_OFF + lane] * __expf(S - dA) * dte;
    }
    __syncthreads();

    // ---- y-pass: own head, rows L1-hot from Phase A ----
    {
        const float* base = hidden + ((size_t)b * T + s0 + hf * 16) * HIDD + h * PP + q;
        float acc = 0.f;
        #pragma unroll
        for (int s = 0; s < 16; s++) acc += sm[WV_OFF + hf * 16 + s] * base[(size_t)s * HIDD];
        sm[PART_OFF + hf * 128 + q] = acc;
    }
    __syncthreads();

    // ---- Broadcast own y slice into every cluster CTA's yall (incl. self) ----
    if (tid < PP) {
        float yv = sm[PART_OFF + tid] + sm[PART_OFF + 128 + tid]
                 + Dv[h] * sm[XL_OFF + h * PP + tid];
        uint32_t laddr = (uint32_t)__cvta_generic_to_shared(sm + YALL_OFF + h * PP + tid);
        #pragma unroll
        for (int r = 0; r < HH; r++) dsmem_store_f32(laddr, r, yv);
    }
    __syncthreads();
    asm volatile("barrier.cluster.arrive.aligned;\n" ::: "memory");

    // ---- Gate silu in the arrive/wait gap: g_W latency hides in cluster skew ----
    {
        const float4* xl4 = (const float4*)(sm + XL_OFF);
        const float4* w4  = (const float4*)(g_W + (size_t)warp * HIDD);
        float v = 0.f;
        #pragma unroll
        for (int k = 0; k < 8; k++) {
            float4 a = xl4[lane + 32 * k], w = w4[lane + 32 * k];
            v += a.x * w.x + a.y * w.y + a.z * w.z + a.w * w.w;
        }
        #pragma unroll
        for (int o = 16; o > 0; o >>= 1) v += __shfl_xor_sync(0xffffffffu, v, o);
        if (lane == 0) {
            float g = tanhf(v + g_bv[warp]);
            sm[SILU_OFF + warp] = g / (1.f + __expf(-g));
        }
    }

    asm volatile("barrier.cluster.wait.aligned;\n" ::: "memory");
    __syncthreads();

    // ---- RMS over all 1024 gated values (local smem now) ----
    float ssq;
    {
        int hd = tid >> 5;                          // head of this float4
        float sg = sm[SILU_OFF + hd];
        float4 yv = ((const float4*)(sm + YALL_OFF))[tid];
        float zx = yv.x * sg, zy = yv.y * sg, zz = yv.z * sg, zw = yv.w * sg;
        ssq = zx * zx + zy * zy + zz * zz + zw * zw;
    }
    #pragma unroll
    for (int o = 16; o > 0; o >>= 1) ssq += __shfl_xor_sync(0xffffffffu, ssq, o);
    if (lane == 0) sm[RED_OFF + warp] = ssq;
    __syncthreads();
    if (tid == 0) {
        float s = 0.f;
        #pragma unroll
        for (int i = 0; i < 8; i++) s += sm[RED_OFF + i];
        sm[SC_OFF] = rsqrtf(s / (float)HIDD + 1e-5f);
    }
    __syncthreads();

    // ---- Own-head normalized z ----
    if (tid < PP)
        sm[ZSH_OFF + tid] = sm[YALL_OFF + h * PP + tid] * sm[SILU_OFF + h] * sm[SC_OFF]
                          * norm_w[h * PP + tid];

    // ---- Projection from the cp.async-staged o_W tile ----
    asm volatile("cp.async.wait_group 0;\n" ::: "memory");
    __syncthreads();
    {
        float acc = 0.f;
        const float* oW = sm + OW_OFF;
        #pragma unroll
        for (int i = 0; i < 64; i++)
            acc += oW[(hf * 64 + i) * PP + q] * sm[ZSH_OFF + hf * 64 + i];
        sm[PART_OFF + hf * 128 + q] = acc;
    }
    __syncthreads();
    if (tid < PP)
        out[b * HIDD + h * PP + tid] = sm[PART_OFF + tid] + sm[PART_OFF + 128 + tid]
                                     + o_bv[h * PP + tid];
}

extern "C" void kernel_launch(void* const* d_in, const int* in_sizes, int n_in,
                              void* d_out, int out_size) {
    const float* hidden  = (const float*)d_in[0];
    const float* dt_W    = (const float*)d_in[1];
    const float* dt_b    = (const float*)d_in[2];
    const float* g_W     = (const float*)d_in[3];
    const float* g_bv    = (const float*)d_in[4];
    const float* A_log   = (const float*)d_in[5];
    const float* Dv      = (const float*)d_in[6];
    const float* dt_bias = (const float*)d_in[7];
    const float* norm_w  = (const float*)d_in[8];
    const float* o_W     = (const float*)d_in[9];
    const float* o_bv    = (const float*)d_in[10];

    int T = in_sizes[0] / (BB * HIDD);   // 4096

    cudaFuncSetAttribute(k_fused, cudaFuncAttributeMaxDynamicSharedMemorySize, SMEM_BYTES);
    k_fused<<<BB * HH, 256, SMEM_BYTES>>>(hidden, dt_W, dt_b, g_W, g_bv, A_log, Dv,
                                          dt_bias, norm_w, o_W, o_bv, (float*)d_out, T);
}

// round 13
// speedup vs baseline: 2.6164x; 1.1678x over previous
#include <cuda_runtime.h>
#include <cstdint>

#define BB   2
#define HH   8
#define PP   128
#define HIDD 1024
#define KWIN 32
#define NTHR 512

// Dynamic smem layout (float offsets); float4-accessed regions 16B aligned.
#define OW_OFF   0                      // 16384 floats (64 KB) o_W[h]
#define XL_OFF   16384                  // 1024 last hidden row
#define YALL_OFF (XL_OFF + 1024)        // 1024 y for all 8 heads (DSMEM target)
#define DTE_OFF  (YALL_OFF + 1024)      // 32
#define DOTS_OFF (DTE_OFF + 32)         // 32
#define WV_OFF   (DOTS_OFF + 32)        // 32
#define ZSH_OFF  (WV_OFF + 32)          // 128
#define PART_OFF (ZSH_OFF + 128)        // 512 (4 groups x 128)
#define SILU_OFF (PART_OFF + 512)       // 8
#define RED_OFF  (SILU_OFF + 8)         // 8
#define SC_OFF   (RED_OFF + 8)          // 4 (1 used)
#define SMEM_FLOATS (SC_OFF + 4)
#define SMEM_BYTES  (SMEM_FLOATS * 4)

__device__ __forceinline__ void dsmem_store_f32(uint32_t local_addr, int rank, float val) {
    uint32_t remote;
    asm volatile("mapa.shared::cluster.u32 %0, %1, %2;\n"
                 : "=r"(remote) : "r"(local_addr), "r"(rank));
    asm volatile("st.shared::cluster.f32 [%0], %1;\n" :: "r"(remote), "f"(val));
}

__global__ void __launch_bounds__(NTHR, 1) __cluster_dims__(HH, 1, 1)
k_fused(const float* __restrict__ hidden,
        const float* __restrict__ dt_W,
        const float* __restrict__ dt_b,
        const float* __restrict__ g_W,
        const float* __restrict__ g_bv,
        const float* __restrict__ A_log,
        const float* __restrict__ Dv,
        const float* __restrict__ dt_bias,
        const float* __restrict__ norm_w,
        const float* __restrict__ o_W,
        const float* __restrict__ o_bv,
        float* __restrict__ out, int T) {
    extern __shared__ __align__(16) float sm[];

    int b = blockIdx.x >> 3, h = blockIdx.x & 7;   // h == cluster rank
    int tid = threadIdx.x, warp = tid >> 5, lane = tid & 31;
    int q = tid & 127, grp = tid >> 7;             // 4 groups of 128
    int s0 = T - KWIN;

    // ---- cp.async: o_W[h] 64 KB -> smem, fully async until the projection ----
    {
        const float4* src = (const float4*)(o_W + (size_t)h * PP * PP);
        uint32_t dst = (uint32_t)__cvta_generic_to_shared(sm + OW_OFF);
        #pragma unroll
        for (int c = 0; c < 8; c++) {
            uint32_t d = dst + (uint32_t)(tid + c * NTHR) * 16u;
            const float4* s = src + tid + c * NTHR;
            asm volatile("cp.async.cg.shared.global [%0], [%1], 16;\n" :: "r"(d), "l"(s));
        }
        asm volatile("cp.async.commit_group;\n" ::: "memory");
    }

    // ---- Stage last hidden row (needed only after the Phase-A sync) ----
    if (tid < HIDD / 4)
        ((float4*)(sm + XL_OFF))[tid] =
            ((const float4*)(hidden + ((size_t)b * T + T - 1) * HIDD))[tid];

    float bias = dt_b[h] + dt_bias[h];
    float Ah   = -__expf(A_log[h]);

    // ---- Phase A: own-head dte + dots, 2 rows per warp, weights via L1 ----
    // No staging sync: dt_W[h] and xlast read straight from global (L1-shared
    // across the 16 warps). float4 index lane+32k: k==h is exactly head h's
    // slice, so dots rides along free.
    {
        const float4* w4  = (const float4*)(dt_W + (size_t)h * HIDD);
        const float4* xlg = (const float4*)(hidden + ((size_t)b * T + T - 1) * HIDD);
        float4 xw = xlg[lane + 32 * h];
        #pragma unroll
        for (int j = 0; j < 2; j++) {
            int s = warp + 16 * j;
            const float4* xr4 = (const float4*)(hidden + ((size_t)b * T + s0 + s) * HIDD);
            float v = 0.f, d = 0.f;
            #pragma unroll
            for (int k = 0; k < 8; k++) {
                float4 a = xr4[lane + 32 * k];
                float4 w = w4[lane + 32 * k];
                v += a.x * w.x + a.y * w.y + a.z * w.z + a.w * w.w;
                if (k == h)
                    d += a.x * xw.x + a.y * xw.y + a.z * xw.z + a.w * xw.w;
            }
            #pragma unroll
            for (int o = 16; o > 0; o >>= 1) {
                v += __shfl_xor_sync(0xffffffffu, v, o);
                d += __shfl_xor_sync(0xffffffffu, d, o);
            }
            if (lane == 0) { sm[DTE_OFF + s] = v + bias; sm[DOTS_OFF + s] = d; }
        }
    }
    __syncthreads();

    // ---- Suffix scan + window weights (warp 0, own head) ----
    if (warp == 0) {
        float dte = sm[DTE_OFF + lane];
        float dA  = dte * Ah;
        float S   = dA;
        #pragma unroll
        for (int o = 1; o < 32; o <<= 1) {
            float t = __shfl_down_sync(0xffffffffu, S, o);
            if (lane + o < 32) S += t;
        }
        // c[s] = S - dA = sum_{r>s} dA[r]
        sm[WV_OFF + lane] = sm[DOTS_OFF + lane] * __expf(S - dA) * dte;
    }
    __syncthreads();

    // ---- y-pass: 4 groups x 8 rows (rows L1-hot from Phase A) ----
    {
        const float* base = hidden + ((size_t)b * T + s0 + grp * 8) * HIDD + h * PP + q;
        float acc = 0.f;
        #pragma unroll
        for (int s = 0; s < 8; s++) acc += sm[WV_OFF + grp * 8 + s] * base[(size_t)s * HIDD];
        sm[PART_OFF + grp * 128 + q] = acc;
    }
    __syncthreads();

    // ---- Broadcast own y slice into every cluster CTA's yall (incl. self) ----
    if (tid < PP) {
        float yv = sm[PART_OFF + tid] + sm[PART_OFF + 128 + tid]
                 + sm[PART_OFF + 256 + tid] + sm[PART_OFF + 384 + tid]
                 + Dv[h] * sm[XL_OFF + h * PP + tid];
        uint32_t laddr = (uint32_t)__cvta_generic_to_shared(sm + YALL_OFF + h * PP + tid);
        #pragma unroll
        for (int r = 0; r < HH; r++) dsmem_store_f32(laddr, r, yv);
    }
    __syncthreads();
    asm volatile("barrier.cluster.arrive.aligned;\n" ::: "memory");

    // ---- Gate silu in the arrive/wait gap (warps 0-7, one head each) ----
    if (warp < HH) {
        const float4* xl4 = (const float4*)(sm + XL_OFF);
        const float4* w4  = (const float4*)(g_W + (size_t)warp * HIDD);
        float v = 0.f;
        #pragma unroll
        for (int k = 0; k < 8; k++) {
            float4 a = xl4[lane + 32 * k], w = w4[lane + 32 * k];
            v += a.x * w.x + a.y * w.y + a.z * w.z + a.w * w.w;
        }
        #pragma unroll
        for (int o = 16; o > 0; o >>= 1) v += __shfl_xor_sync(0xffffffffu, v, o);
        if (lane == 0) {
            float g = tanhf(v + g_bv[warp]);
            sm[SILU_OFF + warp] = g / (1.f + __expf(-g));
        }
    }

    asm volatile("barrier.cluster.wait.aligned;\n" ::: "memory");
    __syncthreads();

    // ---- RMS over all 1024 gated values (warps 0-7, local smem) ----
    if (tid < 256) {
        int hd = tid >> 5;                          // head of this float4
        float sg = sm[SILU_OFF + hd];
        float4 yv = ((const float4*)(sm + YALL_OFF))[tid];
        float zx = yv.x * sg, zy = yv.y * sg, zz = yv.z * sg, zw = yv.w * sg;
        float ssq = zx * zx + zy * zy + zz * zz + zw * zw;
        #pragma unroll
        for (int o = 16; o > 0; o >>= 1) ssq += __shfl_xor_sync(0xffffffffu, ssq, o);
        if (lane == 0) sm[RED_OFF + warp] = ssq;
    }
    __syncthreads();
    if (tid == 0) {
        float s = 0.f;
        #pragma unroll
        for (int i = 0; i < 8; i++) s += sm[RED_OFF + i];
        sm[SC_OFF] = rsqrtf(s / (float)HIDD + 1e-5f);
    }
    __syncthreads();

    // ---- Own-head normalized z ----
    if (tid < PP)
        sm[ZSH_OFF + tid] = sm[YALL_OFF + h * PP + tid] * sm[SILU_OFF + h] * sm[SC_OFF]
                          * norm_w[h * PP + tid];

    // ---- Projection from the cp.async-staged o_W tile (4 groups x 32 rows) ----
    asm volatile("cp.async.wait_group 0;\n" ::: "memory");
    __syncthreads();
    {
        float acc = 0.f;
        const float* oW = sm + OW_OFF;
        #pragma unroll
        for (int i = 0; i < 32; i++)
            acc += oW[(grp * 32 + i) * PP + q] * sm[ZSH_OFF + grp * 32 + i];
        sm[PART_OFF + grp * 128 + q] = acc;
    }
    __syncthreads();
    if (tid < PP)
        out[b * HIDD + h * PP + tid] = sm[PART_OFF + tid] + sm[PART_OFF + 128 + tid]
                                     + sm[PART_OFF + 256 + tid] + sm[PART_OFF + 384 + tid]
                                     + o_bv[h * PP + tid];
}

extern "C" void kernel_launch(void* const* d_in, const int* in_sizes, int n_in,
                              void* d_out, int out_size) {
    const float* hidden  = (const float*)d_in[0];
    const float* dt_W    = (const float*)d_in[1];
    const float* dt_b    = (const float*)d_in[2];
    const float* g_W     = (const float*)d_in[3];
    const float* g_bv    = (const float*)d_in[4];
    const float* A_log   = (const float*)d_in[5];
    const float* Dv      = (const float*)d_in[6];
    const float* dt_bias = (const float*)d_in[7];
    const float* norm_w  = (const float*)d_in[8];
    const float* o_W     = (const float*)d_in[9];
    const float* o_bv    = (const float*)d_in[10];

    int T = in_sizes[0] / (BB * HIDD);   // 4096

    cudaFuncSetAttribute(k_fused, cudaFuncAttributeMaxDynamicSharedMemorySize, SMEM_BYTES);
    k_fused<<<BB * HH, NTHR, SMEM_BYTES>>>(hidden, dt_W, dt_b, g_W, g_bv, A_log, Dv,
                                           dt_bias, norm_w, o_W, o_bv, (float*)d_out, T);
}